// round 5
// baseline (speedup 1.0000x reference)
#include <cuda_runtime.h>
#include <math.h>

// Problem constants
#define B_    4096
#define T_    50
#define I_    17
#define H_    256
#define P_    20
#define M_    32            // batch rows per CTA
#define NGRP_ 2             // thread groups (each owns M_/NGRP_ rows)
#define MG_   (M_ / NGRP_)  // 16 rows per group
#define MT_   8             // row tile per accumulator group
#define NG_   (MG_ / MT_)   // 2 tiles per group
#define NCTA_ (B_ / M_)     // 128 CTAs
#define NTHR_ 512           // 2 groups x 256 columns
#define G4_   (4 * H_)      // 1024 gate rows

#define DT_   0.1f
#define IMGW_ 1920.0f
#define IMGH_ 1080.0f
#define DIAG_ 2202.9071700822507f

// ---------------- transposed-weight scratch (K-major, float4-packed) ----------
// wT[k4][r] = float4( w[r][4*k4 + 0..3] ),  r = g*H + j
__device__ float4 g_w0h[64 * G4_];   // whh0 transposed   (1 MB)
__device__ float4 g_w1i[64 * G4_];   // wih1 transposed   (1 MB)
__device__ float4 g_w1h[64 * G4_];   // whh1 transposed   (1 MB)
__device__ float  g_w0i[I_ * G4_];   // wih0 transposed: g_w0i[k*1024 + r]

__global__ void prep_kernel(const float* __restrict__ whh0,
                            const float* __restrict__ wih1,
                            const float* __restrict__ whh1,
                            const float* __restrict__ wih0)
{
    int idx = blockIdx.x * blockDim.x + threadIdx.x;   // 0 .. 65535
    if (idx < 64 * G4_) {
        int k4 = idx >> 10;
        int r  = idx & (G4_ - 1);
        const float4* s0 = reinterpret_cast<const float4*>(whh0);
        const float4* s1 = reinterpret_cast<const float4*>(wih1);
        const float4* s2 = reinterpret_cast<const float4*>(whh1);
        g_w0h[idx] = s0[r * 64 + k4];
        g_w1i[idx] = s1[r * 64 + k4];
        g_w1h[idx] = s2[r * 64 + k4];
    }
    if (idx < I_ * G4_) {
        int k = idx >> 10;
        int r = idx & (G4_ - 1);
        g_w0i[idx] = wih0[r * I_ + k];
    }
}

// ------------------------------ main kernel ----------------------------------
struct Smem {
    float h0[2][M_][H_];   // layer-0 hidden, double buffered
    float h1[2][M_][H_];   // layer-1 hidden, double buffered
    float c0[M_][H_];      // layer-0 cell
    float c1[M_][H_];      // layer-1 cell
    float xs[M_][I_];      // current timestep input slice
    float raw[M_][2 * P_]; // FC outputs
};
#define SMEM_BYTES (sizeof(Smem))

__device__ __forceinline__ float sigf(float x) {
    return __fdividef(1.f, 1.f + __expf(-x));
}
__device__ __forceinline__ float tanhf_(float x) {
    return __fdividef(2.f, 1.f + __expf(-2.f * x)) - 1.f;
}

// One gb-tile of a GEMV: acc[mt][g] += sum_k wT[k][g*H+j] * hsrc[row][k]
__device__ __forceinline__ void gemv_tile(
    float acc[MT_][4], const float4* __restrict__ wT_j, // = wT + j
    const float (*hsrc)[H_], int row0)
{
#pragma unroll 2
    for (int kc4 = 0; kc4 < 64; ++kc4) {
        float4 w[4];
#pragma unroll
        for (int g = 0; g < 4; ++g)
            w[g] = wT_j[kc4 * G4_ + g * H_];
#pragma unroll
        for (int mt = 0; mt < MT_; ++mt) {
            float4 h = *reinterpret_cast<const float4*>(&hsrc[row0 + mt][kc4 * 4]);
#pragma unroll
            for (int g = 0; g < 4; ++g)
                acc[mt][g] += w[g].x * h.x + w[g].y * h.y +
                              w[g].z * h.z + w[g].w * h.w;
        }
    }
}

__global__ void __launch_bounds__(NTHR_, 1)
lstm_kin_kernel(const float* __restrict__ x,
                const float* __restrict__ bih0, const float* __restrict__ bhh0,
                const float* __restrict__ bih1, const float* __restrict__ bhh1,
                const float* __restrict__ fcw,  const float* __restrict__ fcb,
                float* __restrict__ out)
{
    extern __shared__ float smem_raw[];
    Smem* S = reinterpret_cast<Smem*>(smem_raw);

    const int tid  = threadIdx.x;
    const int j    = tid & (H_ - 1);      // hidden column
    const int grp  = tid >> 8;            // row group (0/1)
    const int row0 = blockIdx.x * M_;
    const int mg0  = grp * MG_;           // first row owned by this group

    float bias0[4], bias1[4];
#pragma unroll
    for (int g = 0; g < 4; ++g) {
        bias0[g] = bih0[g * H_ + j] + bhh0[g * H_ + j];
        bias1[g] = bih1[g * H_ + j] + bhh1[g * H_ + j];
    }

    const float4* __restrict__ w0h_j = g_w0h + j;
    const float4* __restrict__ w1i_j = g_w1i + j;
    const float4* __restrict__ w1h_j = g_w1h + j;

    // Zero this group's state
#pragma unroll
    for (int m = mg0; m < mg0 + MG_; ++m) {
        S->h0[0][m][j] = 0.f;
        S->h1[0][m][j] = 0.f;
        S->c0[m][j]    = 0.f;
        S->c1[m][j]    = 0.f;
    }
    for (int idx = tid; idx < M_ * I_; idx += NTHR_) {
        int m = idx / I_, k = idx % I_;
        S->xs[m][k] = x[((size_t)(row0 + m) * T_ + 0) * I_ + k];
    }
    __syncthreads();

    int cur = 0;
    for (int t = 0; t < T_; ++t) {
        const int nxt = cur ^ 1;

        // ================= layer 0 =================
#pragma unroll 1
        for (int gb = 0; gb < NG_; ++gb) {
            const int r0 = mg0 + gb * MT_;
            float acc[MT_][4];
#pragma unroll
            for (int mt = 0; mt < MT_; ++mt)
#pragma unroll
                for (int g = 0; g < 4; ++g) acc[mt][g] = bias0[g];

            // input contribution (K = 17)
#pragma unroll
            for (int k = 0; k < I_; ++k) {
                float wv0 = g_w0i[k * G4_ + 0 * H_ + j];
                float wv1 = g_w0i[k * G4_ + 1 * H_ + j];
                float wv2 = g_w0i[k * G4_ + 2 * H_ + j];
                float wv3 = g_w0i[k * G4_ + 3 * H_ + j];
#pragma unroll
                for (int mt = 0; mt < MT_; ++mt) {
                    float xv = S->xs[r0 + mt][k];
                    acc[mt][0] += wv0 * xv;
                    acc[mt][1] += wv1 * xv;
                    acc[mt][2] += wv2 * xv;
                    acc[mt][3] += wv3 * xv;
                }
            }
            // recurrent contribution (K = 256)
            gemv_tile(acc, w0h_j, S->h0[cur], r0);

#pragma unroll
            for (int mt = 0; mt < MT_; ++mt) {
                int m = r0 + mt;
                float ig = sigf(acc[mt][0]);
                float fg = sigf(acc[mt][1]);
                float gv = tanhf_(acc[mt][2]);
                float og = sigf(acc[mt][3]);
                float c  = fg * S->c0[m][j] + ig * gv;
                S->c0[m][j]       = c;
                S->h0[nxt][m][j]  = og * tanhf_(c);
            }
        }
        __syncthreads();

        // ================= layer 1 =================
#pragma unroll 1
        for (int gb = 0; gb < NG_; ++gb) {
            const int r0 = mg0 + gb * MT_;
            float acc[MT_][4];
#pragma unroll
            for (int mt = 0; mt < MT_; ++mt)
#pragma unroll
                for (int g = 0; g < 4; ++g) acc[mt][g] = bias1[g];

            gemv_tile(acc, w1i_j, S->h0[nxt], r0);   // wih1 x h0[nxt]
            gemv_tile(acc, w1h_j, S->h1[cur], r0);   // whh1 x h1[cur]

#pragma unroll
            for (int mt = 0; mt < MT_; ++mt) {
                int m = r0 + mt;
                float ig = sigf(acc[mt][0]);
                float fg = sigf(acc[mt][1]);
                float gv = tanhf_(acc[mt][2]);
                float og = sigf(acc[mt][3]);
                float c  = fg * S->c1[m][j] + ig * gv;
                S->c1[m][j]       = c;
                S->h1[nxt][m][j]  = og * tanhf_(c);
            }
        }

        if (t + 1 < T_) {
            for (int idx = tid; idx < M_ * I_; idx += NTHR_) {
                int m = idx / I_, k = idx % I_;
                S->xs[m][k] = x[((size_t)(row0 + m) * T_ + (t + 1)) * I_ + k];
            }
        }
        __syncthreads();
        cur = nxt;
    }

    // ================= FC head =================
    for (int idx = tid; idx < M_ * 2 * P_; idx += NTHR_) {
        int m = idx / (2 * P_), q = idx % (2 * P_);
        const float* wq = fcw + (size_t)q * H_;
        const float* hq = &S->h1[cur][m][0];
        float s = fcb[q];
#pragma unroll 4
        for (int k = 0; k < H_; k += 4) {
            float4 w4 = *reinterpret_cast<const float4*>(wq + k);
            float4 h4 = *reinterpret_cast<const float4*>(hq + k);
            s += w4.x * h4.x + w4.y * h4.y + w4.z * h4.z + w4.w * h4.w;
        }
        S->raw[m][q] = s;
    }
    __syncthreads();

    // ================= kinematic rollout =================
    if (tid < M_) {
        const int m   = tid;
        const int row = row0 + m;
        const float* xl = x + ((size_t)row * T_ + (T_ - 1)) * I_;
        float psi = atan2f(xl[7], xl[8]);
        float X   = xl[0] * IMGW_;
        float Y   = xl[1] * IMGH_;
        float decay = 1.f;
        float* o = out + (size_t)row * P_ * 2;
#pragma unroll 1
        for (int p = 0; p < P_; ++p) {
            float sraw = S->raw[m][2 * p];
            float yaw  = S->raw[m][2 * p + 1];
            float speed = fmaxf(sraw, 0.f) + log1pf(expf(-fabsf(sraw)));
            float w = yaw * decay;
            decay *= 0.97f;
            float v = speed * DIAG_;
            float psi_prev  = psi;
            float psi_after = psi + w * DT_;
            psi = psi_after;
            float is_s  = (fabsf(w) < 0.01f) ? 1.f : 0.f;
            float wsafe = w + is_s * 0.0001f;
            float radius = v / wsafe;
            float sp = sinf(psi_prev),  cp = cosf(psi_prev);
            float sa = sinf(psi_after), ca = cosf(psi_after);
            float dxs = v * cp * DT_;
            float dys = v * sp * DT_;
            float dxt = radius * (sa - sp);
            float dyt = -radius * (ca - cp);
            float dx = is_s * dxs + (1.f - is_s) * dxt;
            float dy = is_s * dys + (1.f - is_s) * dyt;
            X += dx;
            Y += dy;
            o[2 * p]     = X / IMGW_;
            o[2 * p + 1] = Y / IMGH_;
        }
    }
}

extern "C" void kernel_launch(void* const* d_in, const int* in_sizes, int n_in,
                              void* d_out, int out_size)
{
    (void)in_sizes; (void)n_in; (void)out_size;
    const float* x    = (const float*)d_in[0];
    const float* wih0 = (const float*)d_in[1];
    const float* whh0 = (const float*)d_in[2];
    const float* bih0 = (const float*)d_in[3];
    const float* bhh0 = (const float*)d_in[4];
    const float* wih1 = (const float*)d_in[5];
    const float* whh1 = (const float*)d_in[6];
    const float* bih1 = (const float*)d_in[7];
    const float* bhh1 = (const float*)d_in[8];
    const float* fcw  = (const float*)d_in[9];
    const float* fcb  = (const float*)d_in[10];
    float* out = (float*)d_out;

    prep_kernel<<<(64 * G4_ + 255) / 256, 256>>>(whh0, wih1, whh1, wih0);

    cudaFuncSetAttribute(lstm_kin_kernel,
                         cudaFuncAttributeMaxDynamicSharedMemorySize,
                         (int)SMEM_BYTES);

    lstm_kin_kernel<<<NCTA_, NTHR_, SMEM_BYTES>>>(
        x, bih0, bhh0, bih1, bhh1, fcw, fcb, out);
}

// round 8
// speedup vs baseline: 3.3207x; 3.3207x over previous
#include <cuda_runtime.h>
#include <cuda_bf16.h>
#include <math.h>
#include <stdint.h>

#define B_    4096
#define T_    50
#define I_    17
#define H_    256
#define P_    20
#define M_    32
#define NCTA_ 128
#define NTHR_ 512

#define KT0_  18      // GEMM0 k-tiles: 16 (h0) + 2 (x, padded)
#define KT1_  32      // GEMM1 k-tiles: 16 (h0) + 16 (h1)
#define S0_   290     // b0 row stride (bf16 elems), 290/2=145 odd -> conflict-free
#define S1_   258     // b1 row stride
#define SD_   34      // D row stride (floats), odd*2 -> low-conflict

#define DT_   0.1f
#define IMGW_ 1920.0f
#define IMGH_ 1080.0f
#define DIAG_ 2202.9071700822507f

// A-fragment streams, layout [warp16][kt][mt4][hl2][lane32] of uint4 (16B/lane)
__device__ uint4 g_A0[16 * KT0_ * 4 * 2 * 32];   // 1.125 MB
__device__ uint4 g_A1[16 * KT1_ * 4 * 2 * 32];   // 2 MB

// ----------------------------- prep: pack fragments --------------------------
__device__ __forceinline__ unsigned short bfpart(float v, int hl) {
    __nv_bfloat16 h = __float2bfloat16(v);
    if (hl) h = __float2bfloat16(v - __bfloat162float(h));
    return __bfloat16_as_ushort(h);
}
__device__ __forceinline__ unsigned int packw(float a, float b, int hl) {
    return (unsigned int)bfpart(a, hl) | ((unsigned int)bfpart(b, hl) << 16);
}
__device__ __forceinline__ float W0at(const float* whh0, const float* wih0,
                                      int row, int k) {
    if (k < 256) return whh0[row * 256 + k];
    int kk = k - 256;
    return kk < I_ ? wih0[row * I_ + kk] : 0.f;
}
__device__ __forceinline__ float W1at(const float* wih1, const float* whh1,
                                      int row, int k) {
    return k < 256 ? wih1[row * 256 + k] : whh1[row * 256 + (k - 256)];
}

__global__ void prep_kernel(const float* __restrict__ whh0,
                            const float* __restrict__ wih0,
                            const float* __restrict__ wih1,
                            const float* __restrict__ whh1)
{
    int idx = blockIdx.x * blockDim.x + threadIdx.x;
    const int N0 = 16 * KT0_ * 256;            // 73728
    const int N1 = 16 * KT1_ * 256;            // 131072
    if (idx < N0) {
        int w  = idx / (KT0_ * 256);
        int r1 = idx % (KT0_ * 256);
        int kt = r1 >> 8;
        int r2 = r1 & 255;
        int mt = r2 >> 6, hl = (r2 >> 5) & 1, lane = r2 & 31;
        int R = 64 * w + 16 * mt + (lane >> 2);
        int C = 16 * kt + ((lane & 3) << 1);
        uint4 f;
        f.x = packw(W0at(whh0, wih0, R,     C),     W0at(whh0, wih0, R,     C + 1), hl);
        f.y = packw(W0at(whh0, wih0, R + 8, C),     W0at(whh0, wih0, R + 8, C + 1), hl);
        f.z = packw(W0at(whh0, wih0, R,     C + 8), W0at(whh0, wih0, R,     C + 9), hl);
        f.w = packw(W0at(whh0, wih0, R + 8, C + 8), W0at(whh0, wih0, R + 8, C + 9), hl);
        g_A0[idx] = f;
    } else if (idx < N0 + N1) {
        int id = idx - N0;
        int w  = id / (KT1_ * 256);
        int r1 = id % (KT1_ * 256);
        int kt = r1 >> 8;
        int r2 = r1 & 255;
        int mt = r2 >> 6, hl = (r2 >> 5) & 1, lane = r2 & 31;
        int R = 64 * w + 16 * mt + (lane >> 2);
        int C = 16 * kt + ((lane & 3) << 1);
        uint4 f;
        f.x = packw(W1at(wih1, whh1, R,     C),     W1at(wih1, whh1, R,     C + 1), hl);
        f.y = packw(W1at(wih1, whh1, R + 8, C),     W1at(wih1, whh1, R + 8, C + 1), hl);
        f.z = packw(W1at(wih1, whh1, R,     C + 8), W1at(wih1, whh1, R,     C + 9), hl);
        f.w = packw(W1at(wih1, whh1, R + 8, C + 8), W1at(wih1, whh1, R + 8, C + 9), hl);
        g_A1[id] = f;
    }
}

// ------------------------------ main kernel ----------------------------------
struct Smem {
    float D[1024 * SD_];                 // gate pre-activations [row][n], 139264B
    __nv_bfloat16 b0h[32 * S0_];         // B for GEMM0: h0 (k<256) + x (256..272)
    __nv_bfloat16 b0l[32 * S0_];
    __nv_bfloat16 b1h[32 * S1_];         // h1
    __nv_bfloat16 b1l[32 * S1_];
    float raw[M_][2 * P_];
};

__device__ __forceinline__ float sigf(float x) {
    return __fdividef(1.f, 1.f + __expf(-x));
}
__device__ __forceinline__ float tanhf_(float x) {
    return __fdividef(2.f, 1.f + __expf(-2.f * x)) - 1.f;
}

__device__ __forceinline__ void mma16816(float d[4],
    unsigned a0, unsigned a1, unsigned a2, unsigned a3,
    unsigned b0, unsigned b1)
{
    asm volatile(
        "mma.sync.aligned.m16n8k16.row.col.f32.bf16.bf16.f32 "
        "{%0,%1,%2,%3},{%4,%5,%6,%7},{%8,%9},{%0,%1,%2,%3};\n"
        : "+f"(d[0]), "+f"(d[1]), "+f"(d[2]), "+f"(d[3])
        : "r"(a0), "r"(a1), "r"(a2), "r"(a3), "r"(b0), "r"(b1));
}

template<int KT, bool G1>
__device__ __forceinline__ void do_gemm(Smem* S, const uint4* __restrict__ pa,
                                        int warp, int lane)
{
    const int n8 = lane >> 2;
    const int k2 = (lane & 3) << 1;
    float d[4][4][4];
#pragma unroll
    for (int mt = 0; mt < 4; ++mt)
#pragma unroll
        for (int nt = 0; nt < 4; ++nt)
#pragma unroll
            for (int q = 0; q < 4; ++q) d[mt][nt][q] = 0.f;

#pragma unroll 1
    for (int kt = 0; kt < KT; ++kt) {
        const __nv_bfloat16 *bhp, *blp;
        int kb, st;
        if (!G1 || kt < 16) {
            bhp = S->b0h; blp = S->b0l; st = S0_; kb = 16 * kt;
        } else {
            bhp = S->b1h; blp = S->b1l; st = S1_; kb = 16 * (kt - 16);
        }
        unsigned bh[4][2], bl[4][2];
#pragma unroll
        for (int nt = 0; nt < 4; ++nt) {
            int off = (8 * nt + n8) * st + kb + k2;
            bh[nt][0] = *(const unsigned*)(bhp + off);
            bh[nt][1] = *(const unsigned*)(bhp + off + 8);
            bl[nt][0] = *(const unsigned*)(blp + off);
            bl[nt][1] = *(const unsigned*)(blp + off + 8);
        }
#pragma unroll
        for (int mt = 0; mt < 4; ++mt) {
            uint4 ah = pa[((kt * 4 + mt) * 2 + 0) * 32];
            uint4 al = pa[((kt * 4 + mt) * 2 + 1) * 32];
#pragma unroll
            for (int nt = 0; nt < 4; ++nt) {
                mma16816(d[mt][nt], ah.x, ah.y, ah.z, ah.w, bh[nt][0], bh[nt][1]);
                mma16816(d[mt][nt], ah.x, ah.y, ah.z, ah.w, bl[nt][0], bl[nt][1]);
                mma16816(d[mt][nt], al.x, al.y, al.z, al.w, bh[nt][0], bh[nt][1]);
            }
        }
    }
    // store D
#pragma unroll
    for (int mt = 0; mt < 4; ++mt) {
        int row = 64 * warp + 16 * mt + n8;
#pragma unroll
        for (int nt = 0; nt < 4; ++nt) {
            int nc = 8 * nt + k2;
            *(float2*)&S->D[row * SD_ + nc]       = make_float2(d[mt][nt][0], d[mt][nt][1]);
            *(float2*)&S->D[(row + 8) * SD_ + nc] = make_float2(d[mt][nt][2], d[mt][nt][3]);
        }
    }
}

__global__ void __launch_bounds__(NTHR_, 1)
lstm_kin_kernel(const float* __restrict__ x,
                const float* __restrict__ bih0, const float* __restrict__ bhh0,
                const float* __restrict__ bih1, const float* __restrict__ bhh1,
                const float* __restrict__ fcw,  const float* __restrict__ fcb,
                float* __restrict__ out)
{
    extern __shared__ char smem_raw[];
    Smem* S = reinterpret_cast<Smem*>(smem_raw);

    const int tid  = threadIdx.x;
    const int j    = tid & (H_ - 1);
    const int grp  = tid >> 8;
    const int warp = tid >> 5;
    const int lane = tid & 31;
    const int row0 = blockIdx.x * M_;

    float bias0[4], bias1[4];
#pragma unroll
    for (int g = 0; g < 4; ++g) {
        bias0[g] = bih0[g * H_ + j] + bhh0[g * H_ + j];
        bias1[g] = bih1[g * H_ + j] + bhh1[g * H_ + j];
    }

    const uint4* __restrict__ pa0 = g_A0 + (size_t)warp * KT0_ * 256 + lane;
    const uint4* __restrict__ pa1 = g_A1 + (size_t)warp * KT1_ * 256 + lane;

    // zero B buffers (h=0 initial state + pad columns)
    {
        unsigned* z0h = (unsigned*)S->b0h;  unsigned* z0l = (unsigned*)S->b0l;
        for (int i = tid; i < 32 * S0_ / 2; i += NTHR_) { z0h[i] = 0u; z0l[i] = 0u; }
        unsigned* z1h = (unsigned*)S->b1h;  unsigned* z1l = (unsigned*)S->b1l;
        for (int i = tid; i < 32 * S1_ / 2; i += NTHR_) { z1h[i] = 0u; z1l[i] = 0u; }
    }
    // load x(t=0)
    if (tid < M_ * I_) {
        int n = tid / I_, kk = tid % I_;
        float v = x[((size_t)(row0 + n) * T_ + 0) * I_ + kk];
        __nv_bfloat16 hv = __float2bfloat16(v);
        S->b0h[n * S0_ + 256 + kk] = hv;
        S->b0l[n * S0_ + 256 + kk] = __float2bfloat16(v - __bfloat162float(hv));
    }
    __syncthreads();

    float c0r[16], c1r[16];
#pragma unroll
    for (int i = 0; i < 16; ++i) { c0r[i] = 0.f; c1r[i] = 0.f; }

#pragma unroll 1
    for (int t = 0; t < T_; ++t) {
        // ---- GEMM0: D = [whh0|wih0] x [h0;x] ----
        do_gemm<KT0_, false>(S, pa0, warp, lane);
        __syncthreads();

        // ---- epilogue 0: layer-0 cell update ----
#pragma unroll 2
        for (int i = 0; i < 16; ++i) {
            int n = 16 * grp + i;
            float pi = S->D[(0 * 256 + j) * SD_ + n] + bias0[0];
            float pf = S->D[(1 * 256 + j) * SD_ + n] + bias0[1];
            float pg = S->D[(2 * 256 + j) * SD_ + n] + bias0[2];
            float po = S->D[(3 * 256 + j) * SD_ + n] + bias0[3];
            float c  = sigf(pf) * c0r[i] + sigf(pi) * tanhf_(pg);
            c0r[i]   = c;
            float h  = sigf(po) * tanhf_(c);
            __nv_bfloat16 hh = __float2bfloat16(h);
            S->b0h[n * S0_ + j] = hh;
            S->b0l[n * S0_ + j] = __float2bfloat16(h - __bfloat162float(hh));
        }
        // prefetch x(t+1) into b0 x-section (GEMM0 done reading it)
        if (t + 1 < T_ && tid < M_ * I_) {
            int n = tid / I_, kk = tid % I_;
            float v = x[((size_t)(row0 + n) * T_ + (t + 1)) * I_ + kk];
            __nv_bfloat16 hv = __float2bfloat16(v);
            S->b0h[n * S0_ + 256 + kk] = hv;
            S->b0l[n * S0_ + 256 + kk] = __float2bfloat16(v - __bfloat162float(hv));
        }
        __syncthreads();

        // ---- GEMM1: D = [wih1|whh1] x [h0;h1] ----
        do_gemm<KT1_, true>(S, pa1, warp, lane);
        __syncthreads();

        // ---- epilogue 1: layer-1 cell update ----
#pragma unroll 2
        for (int i = 0; i < 16; ++i) {
            int n = 16 * grp + i;
            float pi = S->D[(0 * 256 + j) * SD_ + n] + bias1[0];
            float pf = S->D[(1 * 256 + j) * SD_ + n] + bias1[1];
            float pg = S->D[(2 * 256 + j) * SD_ + n] + bias1[2];
            float po = S->D[(3 * 256 + j) * SD_ + n] + bias1[3];
            float c  = sigf(pf) * c1r[i] + sigf(pi) * tanhf_(pg);
            c1r[i]   = c;
            float h  = sigf(po) * tanhf_(c);
            __nv_bfloat16 hh = __float2bfloat16(h);
            S->b1h[n * S1_ + j] = hh;
            S->b1l[n * S1_ + j] = __float2bfloat16(h - __bfloat162float(hh));
        }
        __syncthreads();
    }

    // ================= FC head: h1 reconstructed from bf16 pair ==============
    for (int idx = tid; idx < M_ * 2 * P_; idx += NTHR_) {
        int m = idx / (2 * P_), q = idx % (2 * P_);
        const float* wq = fcw + (size_t)q * H_;
        float s = fcb[q];
#pragma unroll 4
        for (int k = 0; k < H_; ++k) {
            float hv = __bfloat162float(S->b1h[m * S1_ + k]) +
                       __bfloat162float(S->b1l[m * S1_ + k]);
            s += wq[k] * hv;
        }
        S->raw[m][q] = s;
    }
    __syncthreads();

    // ================= kinematic rollout =================
    if (tid < M_) {
        const int m   = tid;
        const int row = row0 + m;
        const float* xl = x + ((size_t)row * T_ + (T_ - 1)) * I_;
        float psi = atan2f(xl[7], xl[8]);
        float X   = xl[0] * IMGW_;
        float Y   = xl[1] * IMGH_;
        float decay = 1.f;
        float* o = out + (size_t)row * P_ * 2;
#pragma unroll 1
        for (int p = 0; p < P_; ++p) {
            float sraw = S->raw[m][2 * p];
            float yaw  = S->raw[m][2 * p + 1];
            float speed = fmaxf(sraw, 0.f) + log1pf(expf(-fabsf(sraw)));
            float w = yaw * decay;
            decay *= 0.97f;
            float v = speed * DIAG_;
            float psi_prev  = psi;
            float psi_after = psi + w * DT_;
            psi = psi_after;
            float is_s  = (fabsf(w) < 0.01f) ? 1.f : 0.f;
            float wsafe = w + is_s * 0.0001f;
            float radius = v / wsafe;
            float sp = sinf(psi_prev),  cp = cosf(psi_prev);
            float sa = sinf(psi_after), ca = cosf(psi_after);
            float dxs = v * cp * DT_;
            float dys = v * sp * DT_;
            float dxt = radius * (sa - sp);
            float dyt = -radius * (ca - cp);
            float dx = is_s * dxs + (1.f - is_s) * dxt;
            float dy = is_s * dys + (1.f - is_s) * dyt;
            X += dx;
            Y += dy;
            o[2 * p]     = X / IMGW_;
            o[2 * p + 1] = Y / IMGH_;
        }
    }
}

extern "C" void kernel_launch(void* const* d_in, const int* in_sizes, int n_in,
                              void* d_out, int out_size)
{
    (void)in_sizes; (void)n_in; (void)out_size;
    const float* x    = (const float*)d_in[0];
    const float* wih0 = (const float*)d_in[1];
    const float* whh0 = (const float*)d_in[2];
    const float* bih0 = (const float*)d_in[3];
    const float* bhh0 = (const float*)d_in[4];
    const float* wih1 = (const float*)d_in[5];
    const float* whh1 = (const float*)d_in[6];
    const float* bih1 = (const float*)d_in[7];
    const float* bhh1 = (const float*)d_in[8];
    const float* fcw  = (const float*)d_in[9];
    const float* fcb  = (const float*)d_in[10];
    float* out = (float*)d_out;

    const int nprep = 16 * KT0_ * 256 + 16 * KT1_ * 256;
    prep_kernel<<<(nprep + 255) / 256, 256>>>(whh0, wih0, wih1, whh1);

    cudaFuncSetAttribute(lstm_kin_kernel,
                         cudaFuncAttributeMaxDynamicSharedMemorySize,
                         (int)sizeof(Smem));

    lstm_kin_kernel<<<NCTA_, NTHR_, sizeof(Smem)>>>(
        x, bih0, bhh0, bih1, bhh1, fcw, fcb, out);
}

// round 10
// speedup vs baseline: 3.7043x; 1.1155x over previous
#include <cuda_runtime.h>
#include <cuda_bf16.h>
#include <math.h>
#include <stdint.h>

#define B_    4096
#define T_    50
#define I_    17
#define H_    256
#define P_    20
#define M_    32
#define NCTA_ 128
#define NTHR_ 512

#define KT0_  18      // GEMM0 k-tiles: 16 (h0) + 2 (x, padded)
#define KT1_  32      // GEMM1 k-tiles: 16 (h0) + 16 (h1)
#define SH0_  296     // b0 row stride (bf16): k 0..255 = h0, 256..272 = x, rest 0
#define SH1_  264     // b1 row stride (bf16): k 0..255 = h1, rest 0
#define CS_   17      // per-thread c-state stride (floats, odd -> conflict-free)

#define DT_   0.1f
#define IMGW_ 1920.0f
#define IMGH_ 1080.0f
#define DIAG_ 2202.9071700822507f

// A-fragment streams, layout [warp16][kt][mt4][hl2][lane32] of uint4 (16B/lane)
// M-permutation: warp w, m-tile mt=g covers logical rows 256*g + 16*w + r
// (gate g, hidden j = 16w+r) so each thread's D fragment holds all 4 gates
// for its own (j, n) pairs -> in-register epilogue.
__device__ uint4 g_A0[16 * KT0_ * 4 * 2 * 32];   // 1.125 MB
__device__ uint4 g_A1[16 * KT1_ * 4 * 2 * 32];   // 2 MB

// ----------------------------- prep: pack fragments --------------------------
__device__ __forceinline__ unsigned short bfpart(float v, int hl) {
    __nv_bfloat16 h = __float2bfloat16(v);
    if (hl) h = __float2bfloat16(v - __bfloat162float(h));
    return __bfloat16_as_ushort(h);
}
__device__ __forceinline__ unsigned int packw(float a, float b, int hl) {
    return (unsigned int)bfpart(a, hl) | ((unsigned int)bfpart(b, hl) << 16);
}
__device__ __forceinline__ float W0at(const float* whh0, const float* wih0,
                                      int row, int k) {
    if (k < 256) return whh0[row * 256 + k];
    int kk = k - 256;
    return kk < I_ ? wih0[row * I_ + kk] : 0.f;
}
__device__ __forceinline__ float W1at(const float* wih1, const float* whh1,
                                      int row, int k) {
    return k < 256 ? wih1[row * 256 + k] : whh1[row * 256 + (k - 256)];
}

__global__ void prep_kernel(const float* __restrict__ whh0,
                            const float* __restrict__ wih0,
                            const float* __restrict__ wih1,
                            const float* __restrict__ whh1)
{
    int idx = blockIdx.x * blockDim.x + threadIdx.x;
    const int N0 = 16 * KT0_ * 256;
    const int N1 = 16 * KT1_ * 256;
    if (idx < N0) {
        int w  = idx / (KT0_ * 256);
        int r1 = idx % (KT0_ * 256);
        int kt = r1 >> 8;
        int r2 = r1 & 255;
        int mt = r2 >> 6, hl = (r2 >> 5) & 1, lane = r2 & 31;
        int R = 256 * mt + 16 * w + (lane >> 2);       // gate-major permutation
        int C = 16 * kt + ((lane & 3) << 1);
        uint4 f;
        f.x = packw(W0at(whh0, wih0, R,     C),     W0at(whh0, wih0, R,     C + 1), hl);
        f.y = packw(W0at(whh0, wih0, R + 8, C),     W0at(whh0, wih0, R + 8, C + 1), hl);
        f.z = packw(W0at(whh0, wih0, R,     C + 8), W0at(whh0, wih0, R,     C + 9), hl);
        f.w = packw(W0at(whh0, wih0, R + 8, C + 8), W0at(whh0, wih0, R + 8, C + 9), hl);
        g_A0[idx] = f;
    } else if (idx < N0 + N1) {
        int id = idx - N0;
        int w  = id / (KT1_ * 256);
        int r1 = id % (KT1_ * 256);
        int kt = r1 >> 8;
        int r2 = r1 & 255;
        int mt = r2 >> 6, hl = (r2 >> 5) & 1, lane = r2 & 31;
        int R = 256 * mt + 16 * w + (lane >> 2);
        int C = 16 * kt + ((lane & 3) << 1);
        uint4 f;
        f.x = packw(W1at(wih1, whh1, R,     C),     W1at(wih1, whh1, R,     C + 1), hl);
        f.y = packw(W1at(wih1, whh1, R + 8, C),     W1at(wih1, whh1, R + 8, C + 1), hl);
        f.z = packw(W1at(wih1, whh1, R,     C + 8), W1at(wih1, whh1, R,     C + 9), hl);
        f.w = packw(W1at(wih1, whh1, R + 8, C + 8), W1at(wih1, whh1, R + 8, C + 9), hl);
        g_A1[id] = f;
    }
}

// ------------------------------ main kernel ----------------------------------
struct Smem {
    __nv_bfloat16 b0h[2][M_][SH0_];     // h0 + x, double buffered (hi part)
    __nv_bfloat16 b0l[2][M_][SH0_];     // lo part
    __nv_bfloat16 b1h[2][M_][SH1_];     // h1 double buffered
    __nv_bfloat16 b1l[2][M_][SH1_];
    float c0s[NTHR_ * CS_];             // per-thread cell state, layer 0
    float c1s[NTHR_ * CS_];
    float biasS[2][4][H_];              // combined biases [layer][gate][j]
    float raw[M_][2 * P_];
};

__device__ __forceinline__ float sigf(float x) {
    return __fdividef(1.f, 1.f + __expf(-x));
}
__device__ __forceinline__ float tanhf_(float x) {
    return __fdividef(2.f, 1.f + __expf(-2.f * x)) - 1.f;
}

__device__ __forceinline__ void mma16816(float d[4],
    unsigned a0, unsigned a1, unsigned a2, unsigned a3,
    unsigned b0, unsigned b1)
{
    asm volatile(
        "mma.sync.aligned.m16n8k16.row.col.f32.bf16.bf16.f32 "
        "{%0,%1,%2,%3},{%4,%5,%6,%7},{%8,%9},{%0,%1,%2,%3};\n"
        : "+f"(d[0]), "+f"(d[1]), "+f"(d[2]), "+f"(d[3])
        : "r"(a0), "r"(a1), "r"(a2), "r"(a3), "r"(b0), "r"(b1));
}

// GEMM into register fragments. kt<16 reads (bhA,blA,stA) at kb=16kt;
// kt>=16 reads (bhB,blB,stB) at kb=KB2+16*(kt-16).
template<int KT, int KB2>
__device__ __forceinline__ void do_gemm(float (&d)[4][4][4],
    const uint4* __restrict__ pa,
    const __nv_bfloat16* __restrict__ bhA, const __nv_bfloat16* __restrict__ blA,
    const int stA,
    const __nv_bfloat16* __restrict__ bhB, const __nv_bfloat16* __restrict__ blB,
    const int stB, int lane)
{
    const int n8 = lane >> 2;
    const int k2 = (lane & 3) << 1;
#pragma unroll
    for (int mt = 0; mt < 4; ++mt)
#pragma unroll
        for (int nt = 0; nt < 4; ++nt)
#pragma unroll
            for (int q = 0; q < 4; ++q) d[mt][nt][q] = 0.f;

#pragma unroll 1
    for (int kt = 0; kt < KT; ++kt) {
        const __nv_bfloat16 *bhp, *blp;
        int kb, st;
        if (kt < 16) { bhp = bhA; blp = blA; st = stA; kb = 16 * kt; }
        else         { bhp = bhB; blp = blB; st = stB; kb = KB2 + 16 * (kt - 16); }
        unsigned bh[4][2], bl[4][2];
#pragma unroll
        for (int nt = 0; nt < 4; ++nt) {
            int off = (8 * nt + n8) * st + kb + k2;
            bh[nt][0] = *(const unsigned*)(bhp + off);
            bh[nt][1] = *(const unsigned*)(bhp + off + 8);
            bl[nt][0] = *(const unsigned*)(blp + off);
            bl[nt][1] = *(const unsigned*)(blp + off + 8);
        }
#pragma unroll
        for (int mt = 0; mt < 4; ++mt) {
            uint4 ah = pa[((kt * 4 + mt) * 2 + 0) * 32];
            uint4 al = pa[((kt * 4 + mt) * 2 + 1) * 32];
#pragma unroll
            for (int nt = 0; nt < 4; ++nt) {
                mma16816(d[mt][nt], ah.x, ah.y, ah.z, ah.w, bh[nt][0], bh[nt][1]);
                mma16816(d[mt][nt], ah.x, ah.y, ah.z, ah.w, bl[nt][0], bl[nt][1]);
                mma16816(d[mt][nt], al.x, al.y, al.z, al.w, bh[nt][0], bh[nt][1]);
            }
        }
    }
}

// In-register LSTM cell update. d[g][nt][q] holds gate g for
// j = 16*warp + (lane>>2) + 8*(q>>1), n = 8*nt + 2*(lane&3) + (q&1).
__device__ __forceinline__ void epilogue(const float (&d)[4][4][4],
    float* __restrict__ cS, const float* __restrict__ biasL /* [4][H] */,
    __nv_bfloat16* __restrict__ bh, __nv_bfloat16* __restrict__ bl, int st,
    int warp, int lane)
{
    const int jr = lane >> 2;
    const int k2 = (lane & 3) << 1;
    const int ja = 16 * warp + jr;
    float bi[4][2];
#pragma unroll
    for (int g = 0; g < 4; ++g) {
        bi[g][0] = biasL[g * H_ + ja];
        bi[g][1] = biasL[g * H_ + ja + 8];
    }
#pragma unroll
    for (int nt = 0; nt < 4; ++nt) {
#pragma unroll
        for (int q = 0; q < 4; ++q) {
            int jh = q >> 1;
            int j  = ja + 8 * jh;
            int n  = 8 * nt + k2 + (q & 1);
            int ci = nt * 4 + q;
            float pi = d[0][nt][q] + bi[0][jh];
            float pf = d[1][nt][q] + bi[1][jh];
            float pg = d[2][nt][q] + bi[2][jh];
            float po = d[3][nt][q] + bi[3][jh];
            float c  = sigf(pf) * cS[ci] + sigf(pi) * tanhf_(pg);
            cS[ci]   = c;
            float h  = sigf(po) * tanhf_(c);
            __nv_bfloat16 hh = __float2bfloat16(h);
            bh[n * st + j] = hh;
            bl[n * st + j] = __float2bfloat16(h - __bfloat162float(hh));
        }
    }
}

__global__ void __launch_bounds__(NTHR_, 1)
lstm_kin_kernel(const float* __restrict__ x,
                const float* __restrict__ bih0, const float* __restrict__ bhh0,
                const float* __restrict__ bih1, const float* __restrict__ bhh1,
                const float* __restrict__ fcw,  const float* __restrict__ fcb,
                float* __restrict__ out)
{
    extern __shared__ char smem_raw[];
    Smem* S = reinterpret_cast<Smem*>(smem_raw);

    const int tid  = threadIdx.x;
    const int warp = tid >> 5;
    const int lane = tid & 31;
    const int row0 = blockIdx.x * M_;

    const uint4* __restrict__ pa0 = g_A0 + (size_t)warp * KT0_ * 256 + lane;
    const uint4* __restrict__ pa1 = g_A1 + (size_t)warp * KT1_ * 256 + lane;

    // zero all B buffers (initial h = 0 and pad columns), zero c-state
    {
        unsigned* z = (unsigned*)S->b0h;
        const int nb0 = 2 * 2 * M_ * SH0_ / 2;     // b0h + b0l as uints
        for (int i = tid; i < nb0; i += NTHR_) z[i] = 0u;
        unsigned* z1 = (unsigned*)S->b1h;
        const int nb1 = 2 * 2 * M_ * SH1_ / 2;
        for (int i = tid; i < nb1; i += NTHR_) z1[i] = 0u;
    }
    for (int i = tid; i < NTHR_ * CS_; i += NTHR_) { S->c0s[i] = 0.f; S->c1s[i] = 0.f; }
    // combined biases into smem
    for (int i = tid; i < 4 * H_; i += NTHR_) {
        ((float*)S->biasS[0])[i] = bih0[i] + bhh0[i];
        ((float*)S->biasS[1])[i] = bih1[i] + bhh1[i];
    }
    // x(t=0) into b0[0] x-section (cols 256..272) — full 544-element loop
    for (int idx = tid; idx < M_ * I_; idx += NTHR_) {
        int n = idx / I_, kk = idx % I_;
        float v = x[((size_t)(row0 + n) * T_ + 0) * I_ + kk];
        __nv_bfloat16 hv = __float2bfloat16(v);
        S->b0h[0][n][256 + kk] = hv;
        S->b0l[0][n][256 + kk] = __float2bfloat16(v - __bfloat162float(hv));
    }
    __syncthreads();

    float* cS0 = &S->c0s[tid * CS_];
    float* cS1 = &S->c1s[tid * CS_];

    int pb0 = 0, pb1 = 0;
    float d[4][4][4];

#pragma unroll 1
    for (int t = 0; t < T_; ++t) {
        // ---- GEMM0: gates0(t) from h0(t-1) + x(t), both in b0[pb0] ----
        do_gemm<KT0_, 256>(d, pa0,
                           &S->b0h[pb0][0][0], &S->b0l[pb0][0][0], SH0_,
                           &S->b0h[pb0][0][0], &S->b0l[pb0][0][0], SH0_, lane);
        // in-register epilogue 0 -> h0(t) into b0[pb0^1]
        epilogue(d, cS0, &S->biasS[0][0][0],
                 &S->b0h[pb0 ^ 1][0][0], &S->b0l[pb0 ^ 1][0][0], SH0_, warp, lane);
        // prefetch x(t+1) into b0[pb0^1] x-section
        if (t + 1 < T_) {
            for (int idx = tid; idx < M_ * I_; idx += NTHR_) {
                int n = idx / I_, kk = idx % I_;
                float v = x[((size_t)(row0 + n) * T_ + (t + 1)) * I_ + kk];
                __nv_bfloat16 hv = __float2bfloat16(v);
                S->b0h[pb0 ^ 1][n][256 + kk] = hv;
                S->b0l[pb0 ^ 1][n][256 + kk] = __float2bfloat16(v - __bfloat162float(hv));
            }
        }
        __syncthreads();   // the single barrier per step

        // ---- GEMM1: gates1(t) from h0(t) (b0[pb0^1]) and h1(t-1) (b1[pb1]) ----
        do_gemm<KT1_, 0>(d, pa1,
                         &S->b0h[pb0 ^ 1][0][0], &S->b0l[pb0 ^ 1][0][0], SH0_,
                         &S->b1h[pb1][0][0],     &S->b1l[pb1][0][0],     SH1_, lane);
        // in-register epilogue 1 -> h1(t) into b1[pb1^1]
        epilogue(d, cS1, &S->biasS[1][0][0],
                 &S->b1h[pb1 ^ 1][0][0], &S->b1l[pb1 ^ 1][0][0], SH1_, warp, lane);

        pb0 ^= 1; pb1 ^= 1;
    }
    __syncthreads();   // all h1 writes visible for FC head

    // ================= FC head: h1 from bf16 hi/lo pair ======================
    for (int idx = tid; idx < M_ * 2 * P_; idx += NTHR_) {
        int m = idx / (2 * P_), q = idx % (2 * P_);
        const float* wq = fcw + (size_t)q * H_;
        float s = fcb[q];
#pragma unroll 4
        for (int k = 0; k < H_; ++k) {
            float hv = __bfloat162float(S->b1h[pb1][m][k]) +
                       __bfloat162float(S->b1l[pb1][m][k]);
            s += wq[k] * hv;
        }
        S->raw[m][q] = s;
    }
    __syncthreads();

    // ================= kinematic rollout =================
    if (tid < M_) {
        const int m   = tid;
        const int row = row0 + m;
        const float* xl = x + ((size_t)row * T_ + (T_ - 1)) * I_;
        float psi = atan2f(xl[7], xl[8]);
        float X   = xl[0] * IMGW_;
        float Y   = xl[1] * IMGH_;
        float decay = 1.f;
        float* o = out + (size_t)row * P_ * 2;
#pragma unroll 1
        for (int p = 0; p < P_; ++p) {
            float sraw = S->raw[m][2 * p];
            float yaw  = S->raw[m][2 * p + 1];
            float speed = fmaxf(sraw, 0.f) + log1pf(expf(-fabsf(sraw)));
            float w = yaw * decay;
            decay *= 0.97f;
            float v = speed * DIAG_;
            float psi_prev  = psi;
            float psi_after = psi + w * DT_;
            psi = psi_after;
            float is_s  = (fabsf(w) < 0.01f) ? 1.f : 0.f;
            float wsafe = w + is_s * 0.0001f;
            float radius = v / wsafe;
            float sp = sinf(psi_prev),  cp = cosf(psi_prev);
            float sa = sinf(psi_after), ca = cosf(psi_after);
            float dxs = v * cp * DT_;
            float dys = v * sp * DT_;
            float dxt = radius * (sa - sp);
            float dyt = -radius * (ca - cp);
            float dx = is_s * dxs + (1.f - is_s) * dxt;
            float dy = is_s * dys + (1.f - is_s) * dyt;
            X += dx;
            Y += dy;
            o[2 * p]     = X / IMGW_;
            o[2 * p + 1] = Y / IMGH_;
        }
    }
}

extern "C" void kernel_launch(void* const* d_in, const int* in_sizes, int n_in,
                              void* d_out, int out_size)
{
    (void)in_sizes; (void)n_in; (void)out_size;
    const float* x    = (const float*)d_in[0];
    const float* wih0 = (const float*)d_in[1];
    const float* whh0 = (const float*)d_in[2];
    const float* bih0 = (const float*)d_in[3];
    const float* bhh0 = (const float*)d_in[4];
    const float* wih1 = (const float*)d_in[5];
    const float* whh1 = (const float*)d_in[6];
    const float* bih1 = (const float*)d_in[7];
    const float* bhh1 = (const float*)d_in[8];
    const float* fcw  = (const float*)d_in[9];
    const float* fcb  = (const float*)d_in[10];
    float* out = (float*)d_out;

    const int nprep = 16 * KT0_ * 256 + 16 * KT1_ * 256;
    prep_kernel<<<(nprep + 255) / 256, 256>>>(whh0, wih0, wih1, whh1);

    cudaFuncSetAttribute(lstm_kin_kernel,
                         cudaFuncAttributeMaxDynamicSharedMemorySize,
                         (int)sizeof(Smem));

    lstm_kin_kernel<<<NCTA_, NTHR_, sizeof(Smem)>>>(
        x, bih0, bhh0, bih1, bhh1, fcw, fcb, out);
}